// round 6
// baseline (speedup 1.0000x reference)
#include <cuda_runtime.h>

#define N_NODES 50000
#define M_NB    16
#define NCAPS   8
#define NHID    16
#define DIM     128
#define ROUTIT  6

#define FULLMASK 0xffffffffu

// Scratch (no allocation allowed): static device buffers.
__device__ float g_xn[N_NODES * DIM];  // normalized layer-0 input
__device__ float g_h1[N_NODES * DIM];  // layer-0 routing output (relu'd)
__device__ float g_y [N_NODES * DIM];  // normalize(relu(fc(h1)))

// ---- f32x2 packed helpers (sm_103a) ---------------------------------------
__device__ __forceinline__ unsigned long long fma2(unsigned long long a,
                                                   unsigned long long b,
                                                   unsigned long long c)
{
    unsigned long long d;
    asm("fma.rn.f32x2 %0, %1, %2, %3;" : "=l"(d) : "l"(a), "l"(b), "l"(c));
    return d;
}
__device__ __forceinline__ unsigned long long add2(unsigned long long a,
                                                   unsigned long long b)
{
    unsigned long long d;
    asm("add.rn.f32x2 %0, %1, %2;" : "=l"(d) : "l"(a), "l"(b));
    return d;
}
__device__ __forceinline__ unsigned long long mul2(unsigned long long a,
                                                   unsigned long long b)
{
    unsigned long long d;
    asm("mul.rn.f32x2 %0, %1, %2;" : "=l"(d) : "l"(a), "l"(b));
    return d;
}
__device__ __forceinline__ unsigned long long pack2(float lo, float hi)
{
    unsigned long long d;
    asm("mov.b64 %0, {%1, %2};" : "=l"(d) : "f"(lo), "f"(hi));
    return d;
}
__device__ __forceinline__ void unpack2(unsigned long long v, float& lo, float& hi)
{
    asm("mov.b64 {%0, %1}, %2;" : "=f"(lo), "=f"(hi) : "l"(v));
}

// ---------------------------------------------------------------------------
// K1: per-capsule L2 normalize of raw x -> g_xn
// ---------------------------------------------------------------------------
__global__ __launch_bounds__(256) void normalize_kernel(const float* __restrict__ x)
{
    int idx = blockIdx.x * blockDim.x + threadIdx.x;       // capsule index
    if (idx >= N_NODES * NCAPS) return;
    const float4* src = reinterpret_cast<const float4*>(x) + idx * 4;
    float4 v0 = src[0], v1 = src[1], v2 = src[2], v3 = src[3];
    float ss = v0.x*v0.x + v0.y*v0.y + v0.z*v0.z + v0.w*v0.w
             + v1.x*v1.x + v1.y*v1.y + v1.z*v1.z + v1.w*v1.w
             + v2.x*v2.x + v2.y*v2.y + v2.z*v2.z + v2.w*v2.w
             + v3.x*v3.x + v3.y*v3.y + v3.z*v3.z + v3.w*v3.w;
    float inv = rsqrtf(fmaxf(ss, 1e-24f));
    float4* dst = reinterpret_cast<float4*>(g_xn) + idx * 4;
    v0.x*=inv; v0.y*=inv; v0.z*=inv; v0.w*=inv;
    v1.x*=inv; v1.y*=inv; v1.z*=inv; v1.w*=inv;
    v2.x*=inv; v2.y*=inv; v2.z*=inv; v2.w*=inv;
    v3.x*=inv; v3.y*=inv; v3.z*=inv; v3.w*=inv;
    dst[0]=v0; dst[1]=v1; dst[2]=v2; dst[3]=v3;
}

// ---------------------------------------------------------------------------
// Warp-per-node routing. Lane L: capsule k = L>>2, dg = L&3, q = (L>>2)&3.
// Fully permuted gather: register slot s = 4i+c holds z of neighbor
//   m = s ^ (lane & 15)  ==  4*(i^q) + (c^dg).
// => phase-A reduce-scatter (over dg, masks 2,1), softmax k-reduction
//    (RS masks 8,4 + allreduce 16 + AG 8,4) and the p-allgather are ALL
//    select-free with compile-time register indices.
// sdot[i] = full dot for m = 4(i^q)+(dg^3); e[i] and t[i] share the slot
// labeling so the division aligns; slot c=0/1/2/3 of m-group i pairs with
// pD/pB/pC/pA respectively in phase B (unchanged from previous round).
// ---------------------------------------------------------------------------
__device__ __forceinline__ void routing_warp(const float* __restrict__ src,
                                             const int*   __restrict__ nb,
                                             float*       __restrict__ out,
                                             int node)
{
    const int lane = threadIdx.x & 31;
    const int perm = lane & 15;            // 4q | dg

    // Broadcast neighbor indices: lanes 0..15 load one each.
    int nbv = 0;
    if (lane < 16) nbv = nb[node * M_NB + lane];

    const ulonglong2* srcv = reinterpret_cast<const ulonglong2*>(src);

    // xn / u init: this lane's 4 floats as two f32x2 pairs.
    ulonglong2 xn = srcv[node * 32 + lane];
    ulonglong2 u  = xn;

    // Gather z with (q,dg)-permuted slots (coalesced 16B per lane per row).
    ulonglong2 z[M_NB];
#pragma unroll
    for (int s = 0; s < M_NB; s++) {
        int row = __shfl_sync(FULLMASK, nbv, s ^ perm);
        z[s] = srcv[row * 32 + lane];
    }

    const unsigned long long ZERO = 0;
    ulonglong2 unew = xn;

#pragma unroll
    for (int it = 0; it < ROUTIT; it++) {
        // ---- phase A: partial dots (own 4 dims) for each slot ----
        float a[M_NB];
#pragma unroll
        for (int s = 0; s < M_NB; s++) {
            unsigned long long acc = fma2(z[s].x, u.x, fma2(z[s].y, u.y, ZERO));
            float lo, hi; unpack2(acc, lo, hi);
            a[s] = lo + hi;
        }

        // ---- select-free reduce-scatter over the 4 dg-lanes (masks 2,1) ----
        float b[8];
#pragma unroll
        for (int i = 0; i < 4; i++) {
#pragma unroll
            for (int c0 = 0; c0 < 2; c0++) {
                b[2*i + c0] = a[4*i + (c0 ^ 2)]
                            + __shfl_xor_sync(FULLMASK, a[4*i + c0], 2);
            }
        }
        float sdot[4];
#pragma unroll
        for (int i = 0; i < 4; i++) {
            sdot[i] = b[2*i + 1] + __shfl_xor_sync(FULLMASK, b[2*i + 0], 1);
        }
        // sdot[i] = <z[m], u> for m = 4(i^q) + (dg^3).

        // ---- softmax over k. |s|<=1 (unit vectors): no max subtraction.
        //      k-sum via RS(8,4) + allreduce(16) + AG(8,4): 7 shfl, 4 add. ----
        float e[4];
#pragma unroll
        for (int i = 0; i < 4; i++) e[i] = __expf(sdot[i]);

        float f0 = e[0 ^ 2] + __shfl_xor_sync(FULLMASK, e[0], 8);
        float f1 = e[1 ^ 2] + __shfl_xor_sync(FULLMASK, e[1], 8);
        float g  = f1 + __shfl_xor_sync(FULLMASK, f0, 4);
        float t3 = g  + __shfl_xor_sync(FULLMASK, g, 16);   // slot 3 sum
        float t1 = __shfl_xor_sync(FULLMASK, t3, 8);        // slot 1
        float t2 = __shfl_xor_sync(FULLMASK, t3, 4);        // slot 2
        float t0 = __shfl_xor_sync(FULLMASK, t1, 4);        // slot 0

        float pA[4];
        pA[0] = __fdividef(e[0], t0);
        pA[1] = __fdividef(e[1], t1);
        pA[2] = __fdividef(e[2], t2);
        pA[3] = __fdividef(e[3], t3);
        // pA[i] ↔ m-group i (slotwise), offset dg^3.

        // ---- depth-1 allgather of p over the dg-group ----
        float pB[4], pC[4], pD[4];
#pragma unroll
        for (int i = 0; i < 4; i++) pB[i] = __shfl_xor_sync(FULLMASK, pA[i], 2); // offset dg^1
#pragma unroll
        for (int i = 0; i < 4; i++) pC[i] = __shfl_xor_sync(FULLMASK, pA[i], 1); // offset dg^2
#pragma unroll
        for (int i = 0; i < 4; i++) pD[i] = __shfl_xor_sync(FULLMASK, pA[i], 3); // offset dg

        // ---- phase B: unew = xn + sum_m p[m] * z[m] (packed, 2 chains) ----
        ulonglong2 accA = xn;
        ulonglong2 accB; accB.x = ZERO; accB.y = ZERO;
#pragma unroll
        for (int i = 0; i < 4; i++) {
            unsigned long long w0 = pack2(pD[i], pD[i]);   // slot c=0 ↔ offset dg
            accA.x = fma2(z[4*i + 0].x, w0, accA.x);
            accA.y = fma2(z[4*i + 0].y, w0, accA.y);
            unsigned long long w1 = pack2(pB[i], pB[i]);   // slot c=1 ↔ dg^1
            accA.x = fma2(z[4*i + 1].x, w1, accA.x);
            accA.y = fma2(z[4*i + 1].y, w1, accA.y);
            unsigned long long w2 = pack2(pC[i], pC[i]);   // slot c=2 ↔ dg^2
            accB.x = fma2(z[4*i + 2].x, w2, accB.x);
            accB.y = fma2(z[4*i + 2].y, w2, accB.y);
            unsigned long long w3 = pack2(pA[i], pA[i]);   // slot c=3 ↔ dg^3
            accB.x = fma2(z[4*i + 3].x, w3, accB.x);
            accB.y = fma2(z[4*i + 3].y, w3, accB.y);
        }
        unew.x = add2(accA.x, accB.x);
        unew.y = add2(accA.y, accB.y);

        if (it < ROUTIT - 1) {
            // per-capsule renormalize: ||unew||^2 over the 4 dg-lanes
            unsigned long long sq = fma2(unew.x, unew.x, fma2(unew.y, unew.y, ZERO));
            float lo, hi; unpack2(sq, lo, hi);
            float nsq = lo + hi;
            nsq += __shfl_xor_sync(FULLMASK, nsq, 1);
            nsq += __shfl_xor_sync(FULLMASK, nsq, 2);
            float inv = rsqrtf(fmaxf(nsq, 1e-24f));
            unsigned long long invp = pack2(inv, inv);
            u.x = mul2(unew.x, invp);
            u.y = mul2(unew.y, invp);
        }
    }

    // relu + store
    float f0o, f1o, f2o, f3o;
    unpack2(unew.x, f0o, f1o);
    unpack2(unew.y, f2o, f3o);
    float4 o;
    o.x = fmaxf(f0o, 0.f); o.y = fmaxf(f1o, 0.f);
    o.z = fmaxf(f2o, 0.f); o.w = fmaxf(f3o, 0.f);
    reinterpret_cast<float4*>(out)[node * 32 + lane] = o;
}

__global__ __launch_bounds__(128, 5) void routing1_kernel(const int* __restrict__ nb)
{
    routing_warp(g_xn, nb, g_h1, blockIdx.x * 4 + (threadIdx.x >> 5));
}

__global__ __launch_bounds__(128, 5) void routing2_kernel(const int* __restrict__ nb,
                                                          float* __restrict__ out)
{
    routing_warp(g_y, nb, out, blockIdx.x * 4 + (threadIdx.x >> 5));
}

// ---------------------------------------------------------------------------
// K3: y = normalize_per_capsule( relu( h1 @ W^T + b ) )  -> g_y
// Block: 32 nodes x 128 cols. 256 threads, each computes 4 nodes x 4 cols.
// Inner product in packed f32x2 (2 FFMA2 per node per kk instead of 4 FFMA).
// ---------------------------------------------------------------------------
__global__ __launch_bounds__(256) void fc_kernel(const float* __restrict__ W,
                                                 const float* __restrict__ bias)
{
    __shared__ __align__(16) float Hs[32 * 36];     // Hs[node*36 + kk]
    __shared__ __align__(16) float Ws[32 * 132];    // Ws[kk*132 + j]  (transposed)

    const int t    = threadIdx.x;
    const int row0 = blockIdx.x * 32;
    const int ng   = t >> 5;        // warp id = node group (4 nodes)
    const int cg   = t & 31;        // col group (4 cols)
    const int c0   = cg * 4;

    ulonglong2 accp[4];
#pragma unroll
    for (int i = 0; i < 4; i++) { accp[i].x = 0ull; accp[i].y = 0ull; }

    float bv[4];
#pragma unroll
    for (int j = 0; j < 4; j++) bv[j] = bias[c0 + j];

    const int lr = t >> 3;          // 0..31
    const int lc = t & 7;           // 0..7

    for (int kt = 0; kt < 4; kt++) {
        {
            int gr = row0 + lr;
            float4 hv = make_float4(0.f, 0.f, 0.f, 0.f);
            if (gr < N_NODES)
                hv = *reinterpret_cast<const float4*>(g_h1 + gr * DIM + kt * 32 + lc * 4);
            *reinterpret_cast<float4*>(Hs + lr * 36 + lc * 4) = hv;
        }
#pragma unroll
        for (int r = 0; r < 4; r++) {
            int j = lr + 32 * r;
            float4 wv = *reinterpret_cast<const float4*>(W + j * DIM + kt * 32 + lc * 4);
            Ws[(lc * 4 + 0) * 132 + j] = wv.x;
            Ws[(lc * 4 + 1) * 132 + j] = wv.y;
            Ws[(lc * 4 + 2) * 132 + j] = wv.z;
            Ws[(lc * 4 + 3) * 132 + j] = wv.w;
        }
        __syncthreads();

#pragma unroll
        for (int kk = 0; kk < 32; kk++) {
            ulonglong2 wq = *reinterpret_cast<const ulonglong2*>(Ws + kk * 132 + c0);
#pragma unroll
            for (int i = 0; i < 4; i++) {
                float h = Hs[(ng * 4 + i) * 36 + kk];
                unsigned long long hp = pack2(h, h);
                accp[i].x = fma2(hp, wq.x, accp[i].x);
                accp[i].y = fma2(hp, wq.y, accp[i].y);
            }
        }
        __syncthreads();
    }

#pragma unroll
    for (int i = 0; i < 4; i++) {
        float a0, a1, a2, a3;
        unpack2(accp[i].x, a0, a1);
        unpack2(accp[i].y, a2, a3);
        float v0 = fmaxf(a0 + bv[0], 0.f);
        float v1 = fmaxf(a1 + bv[1], 0.f);
        float v2 = fmaxf(a2 + bv[2], 0.f);
        float v3 = fmaxf(a3 + bv[3], 0.f);
        float ss = v0*v0 + v1*v1 + v2*v2 + v3*v3;
        ss += __shfl_xor_sync(FULLMASK, ss, 1);
        ss += __shfl_xor_sync(FULLMASK, ss, 2);
        float inv = rsqrtf(fmaxf(ss, 1e-24f));
        int gr = row0 + ng * 4 + i;
        if (gr < N_NODES) {
            *reinterpret_cast<float4*>(g_y + gr * DIM + c0) =
                make_float4(v0 * inv, v1 * inv, v2 * inv, v3 * inv);
        }
    }
}

// ---------------------------------------------------------------------------
extern "C" void kernel_launch(void* const* d_in, const int* in_sizes, int n_in,
                              void* d_out, int out_size)
{
    const float* x  = (const float*)d_in[0];
    const int*   nb = (const int*)  d_in[1];
    const float* w  = (const float*)d_in[2];
    const float* b  = (const float*)d_in[3];
    float* out = (float*)d_out;

    (void)in_sizes; (void)n_in; (void)out_size;

    int ncaps_total = N_NODES * NCAPS;
    normalize_kernel<<<(ncaps_total + 255) / 256, 256>>>(x);
    routing1_kernel<<<N_NODES / 4, 128>>>(nb);        // 50000 = 12500 * 4
    fc_kernel<<<(N_NODES + 31) / 32, 256>>>(w, b);
    routing2_kernel<<<N_NODES / 4, 128>>>(nb, out);
}

// round 9
// speedup vs baseline: 1.1286x; 1.1286x over previous
#include <cuda_runtime.h>

#define N_NODES 50000
#define M_NB    16
#define NCAPS   8
#define NHID    16
#define DIM     128
#define ROUTIT  6

#define FULLMASK 0xffffffffu

// Scratch (no allocation allowed): static device buffers.
__device__ float g_xn[N_NODES * DIM];  // normalized layer-0 input
__device__ float g_h1[N_NODES * DIM];  // layer-0 routing output (relu'd)
__device__ float g_y [N_NODES * DIM];  // normalize(relu(fc(h1)))

// ---- f32x2 packed helpers (sm_103a) ---------------------------------------
__device__ __forceinline__ unsigned long long fma2(unsigned long long a,
                                                   unsigned long long b,
                                                   unsigned long long c)
{
    unsigned long long d;
    asm("fma.rn.f32x2 %0, %1, %2, %3;" : "=l"(d) : "l"(a), "l"(b), "l"(c));
    return d;
}
__device__ __forceinline__ unsigned long long add2(unsigned long long a,
                                                   unsigned long long b)
{
    unsigned long long d;
    asm("add.rn.f32x2 %0, %1, %2;" : "=l"(d) : "l"(a), "l"(b));
    return d;
}
__device__ __forceinline__ unsigned long long mul2(unsigned long long a,
                                                   unsigned long long b)
{
    unsigned long long d;
    asm("mul.rn.f32x2 %0, %1, %2;" : "=l"(d) : "l"(a), "l"(b));
    return d;
}
__device__ __forceinline__ unsigned long long pack2(float lo, float hi)
{
    unsigned long long d;
    asm("mov.b64 %0, {%1, %2};" : "=l"(d) : "f"(lo), "f"(hi));
    return d;
}
__device__ __forceinline__ void unpack2(unsigned long long v, float& lo, float& hi)
{
    asm("mov.b64 {%0, %1}, %2;" : "=f"(lo), "=f"(hi) : "l"(v));
}

// ---------------------------------------------------------------------------
// K1: per-capsule L2 normalize of raw x -> g_xn
// ---------------------------------------------------------------------------
__global__ __launch_bounds__(256) void normalize_kernel(const float* __restrict__ x)
{
    int idx = blockIdx.x * blockDim.x + threadIdx.x;       // capsule index
    if (idx >= N_NODES * NCAPS) return;
    const float4* src = reinterpret_cast<const float4*>(x) + idx * 4;
    float4 v0 = src[0], v1 = src[1], v2 = src[2], v3 = src[3];
    float ss = v0.x*v0.x + v0.y*v0.y + v0.z*v0.z + v0.w*v0.w
             + v1.x*v1.x + v1.y*v1.y + v1.z*v1.z + v1.w*v1.w
             + v2.x*v2.x + v2.y*v2.y + v2.z*v2.z + v2.w*v2.w
             + v3.x*v3.x + v3.y*v3.y + v3.z*v3.z + v3.w*v3.w;
    float inv = rsqrtf(fmaxf(ss, 1e-24f));
    float4* dst = reinterpret_cast<float4*>(g_xn) + idx * 4;
    v0.x*=inv; v0.y*=inv; v0.z*=inv; v0.w*=inv;
    v1.x*=inv; v1.y*=inv; v1.z*=inv; v1.w*=inv;
    v2.x*=inv; v2.y*=inv; v2.z*=inv; v2.w*=inv;
    v3.x*=inv; v3.y*=inv; v3.z*=inv; v3.w*=inv;
    dst[0]=v0; dst[1]=v1; dst[2]=v2; dst[3]=v3;
}

// ---------------------------------------------------------------------------
// Warp-per-node routing (R5 structure). Lane L: capsule k = L>>2, dg = L&3.
// Permuted gather: register slot s holds z of neighbor m = (s&~3)|((s&3)^dg)
// => butterfly reduce-scatter and p-allgather need NO runtime selects.
// After reduce-scatter, sdot[i] is the full dot for m = 4i + (dg^3).
// p = e / t computed PER-SLOT (each m keeps its own denominator), THEN
// allgathered depth-1: pB=xor2 ↔ dg^1, pC=xor1 ↔ dg^2, pD=xor3 ↔ dg.
// Slot c=0/1/2/3 uses pD/pB/pC/pA (compile-time mapping).
// ---------------------------------------------------------------------------
__device__ __forceinline__ void routing_warp(const float* __restrict__ src,
                                             const int*   __restrict__ nb,
                                             float*       __restrict__ out,
                                             int node)
{
    const int lane = threadIdx.x & 31;
    const int dg   = lane & 3;

    // Broadcast neighbor indices: lanes 0..15 load one each.
    int nbv = 0;
    if (lane < 16) nbv = nb[node * M_NB + lane];

    const ulonglong2* srcv = reinterpret_cast<const ulonglong2*>(src);

    // xn / u init: this lane's 4 floats as two f32x2 pairs.
    ulonglong2 xn = srcv[node * 32 + lane];
    ulonglong2 u  = xn;

    // Gather z with dg-permuted slots (coalesced 16B per lane per row).
    ulonglong2 z[M_NB];
#pragma unroll
    for (int s = 0; s < M_NB; s++) {
        int row = __shfl_sync(FULLMASK, nbv, s ^ dg);
        z[s] = srcv[row * 32 + lane];
    }

    const unsigned long long ZERO = 0;
    ulonglong2 unew = xn;

#pragma unroll
    for (int it = 0; it < ROUTIT; it++) {
        // ---- phase A: partial dots (own 4 dims) for each slot ----
        float a[M_NB];
#pragma unroll
        for (int s = 0; s < M_NB; s++) {
            unsigned long long acc = fma2(z[s].x, u.x, fma2(z[s].y, u.y, ZERO));
            float lo, hi; unpack2(acc, lo, hi);
            a[s] = lo + hi;
        }

        // ---- select-free reduce-scatter over the 4 dg-lanes ----
        float b[8];
#pragma unroll
        for (int i = 0; i < 4; i++) {
#pragma unroll
            for (int c0 = 0; c0 < 2; c0++) {
                b[2*i + c0] = a[4*i + (c0 ^ 2)]
                            + __shfl_xor_sync(FULLMASK, a[4*i + c0], 2);
            }
        }
        float sdot[4];
#pragma unroll
        for (int i = 0; i < 4; i++) {
            sdot[i] = b[2*i + 1] + __shfl_xor_sync(FULLMASK, b[2*i + 0], 1);
        }
        // sdot[i] = <z[m], u> for m = 4*i + (dg^3).

        // ---- softmax over k (8 lanes, stride 4). |s|<=1 (unit vectors):
        //      shift-invariant softmax needs no max subtraction. ----
        float e[4], t[4];
#pragma unroll
        for (int i = 0; i < 4; i++) { e[i] = __expf(sdot[i]); t[i] = e[i]; }
#pragma unroll
        for (int i = 0; i < 4; i++) t[i] += __shfl_xor_sync(FULLMASK, t[i], 4);
#pragma unroll
        for (int i = 0; i < 4; i++) t[i] += __shfl_xor_sync(FULLMASK, t[i], 8);
#pragma unroll
        for (int i = 0; i < 4; i++) t[i] += __shfl_xor_sync(FULLMASK, t[i], 16);
        float pA[4];
#pragma unroll
        for (int i = 0; i < 4; i++) pA[i] = __fdividef(e[i], t[i]);
        // pA[i] ↔ m-offset dg^3 (per-m denominator applied per slot).

        // ---- depth-1 allgather of p over the dg-group ----
        float pB[4], pC[4], pD[4];
#pragma unroll
        for (int i = 0; i < 4; i++) pB[i] = __shfl_xor_sync(FULLMASK, pA[i], 2); // offset dg^1
#pragma unroll
        for (int i = 0; i < 4; i++) pC[i] = __shfl_xor_sync(FULLMASK, pA[i], 1); // offset dg^2
#pragma unroll
        for (int i = 0; i < 4; i++) pD[i] = __shfl_xor_sync(FULLMASK, pA[i], 3); // offset dg

        // ---- phase B: unew = xn + sum_m p[m] * z[m] (packed, 2 chains) ----
        ulonglong2 accA = xn;
        ulonglong2 accB; accB.x = ZERO; accB.y = ZERO;
#pragma unroll
        for (int i = 0; i < 4; i++) {
            unsigned long long w0 = pack2(pD[i], pD[i]);   // slot c=0 ↔ offset dg
            accA.x = fma2(z[4*i + 0].x, w0, accA.x);
            accA.y = fma2(z[4*i + 0].y, w0, accA.y);
            unsigned long long w1 = pack2(pB[i], pB[i]);   // slot c=1 ↔ dg^1
            accA.x = fma2(z[4*i + 1].x, w1, accA.x);
            accA.y = fma2(z[4*i + 1].y, w1, accA.y);
            unsigned long long w2 = pack2(pC[i], pC[i]);   // slot c=2 ↔ dg^2
            accB.x = fma2(z[4*i + 2].x, w2, accB.x);
            accB.y = fma2(z[4*i + 2].y, w2, accB.y);
            unsigned long long w3 = pack2(pA[i], pA[i]);   // slot c=3 ↔ dg^3
            accB.x = fma2(z[4*i + 3].x, w3, accB.x);
            accB.y = fma2(z[4*i + 3].y, w3, accB.y);
        }
        unew.x = add2(accA.x, accB.x);
        unew.y = add2(accA.y, accB.y);

        if (it < ROUTIT - 1) {
            // per-capsule renormalize: ||unew||^2 over the 4 dg-lanes
            unsigned long long sq = fma2(unew.x, unew.x, fma2(unew.y, unew.y, ZERO));
            float lo, hi; unpack2(sq, lo, hi);
            float nsq = lo + hi;
            nsq += __shfl_xor_sync(FULLMASK, nsq, 1);
            nsq += __shfl_xor_sync(FULLMASK, nsq, 2);
            float inv = rsqrtf(fmaxf(nsq, 1e-24f));
            unsigned long long invp = pack2(inv, inv);
            u.x = mul2(unew.x, invp);
            u.y = mul2(unew.y, invp);
        }
    }

    // relu + store
    float f0, f1, f2, f3;
    unpack2(unew.x, f0, f1);
    unpack2(unew.y, f2, f3);
    float4 o;
    o.x = fmaxf(f0, 0.f); o.y = fmaxf(f1, 0.f);
    o.z = fmaxf(f2, 0.f); o.w = fmaxf(f3, 0.f);
    reinterpret_cast<float4*>(out)[node * 32 + lane] = o;
}

__global__ __launch_bounds__(128, 5) void routing1_kernel(const int* __restrict__ nb)
{
    routing_warp(g_xn, nb, g_h1, blockIdx.x * 4 + (threadIdx.x >> 5));
}

__global__ __launch_bounds__(128, 5) void routing2_kernel(const int* __restrict__ nb,
                                                          float* __restrict__ out)
{
    routing_warp(g_y, nb, out, blockIdx.x * 4 + (threadIdx.x >> 5));
}

// ---------------------------------------------------------------------------
// K3: y = normalize_per_capsule( relu( h1 @ W^T + b ) )  -> g_y
// Block: 32 nodes x 128 cols. 256 threads, each computes 4 nodes x 4 cols.
// Inner loop register-blocked over groups of 4 kk: per group, 4x LDS.128
// from Hs (warp-broadcast) + 4x LDS.128 from Ws -> 8 LDS per 4 kk
// (vs 20 before), FMA in packed f32x2.
// ---------------------------------------------------------------------------
__global__ __launch_bounds__(256) void fc_kernel(const float* __restrict__ W,
                                                 const float* __restrict__ bias)
{
    __shared__ __align__(16) float Hs[32 * 36];     // Hs[node*36 + kk]
    __shared__ __align__(16) float Ws[32 * 132];    // Ws[kk*132 + j]  (transposed)

    const int t    = threadIdx.x;
    const int row0 = blockIdx.x * 32;
    const int ng   = t >> 5;        // warp id = node group (4 nodes)
    const int cg   = t & 31;        // col group (4 cols)
    const int c0   = cg * 4;

    ulonglong2 accp[4];
#pragma unroll
    for (int i = 0; i < 4; i++) { accp[i].x = 0ull; accp[i].y = 0ull; }

    float bv[4];
#pragma unroll
    for (int j = 0; j < 4; j++) bv[j] = bias[c0 + j];

    const int lr = t >> 3;          // 0..31
    const int lc = t & 7;           // 0..7

    for (int kt = 0; kt < 4; kt++) {
        {
            int gr = row0 + lr;
            float4 hv = make_float4(0.f, 0.f, 0.f, 0.f);
            if (gr < N_NODES)
                hv = *reinterpret_cast<const float4*>(g_h1 + gr * DIM + kt * 32 + lc * 4);
            *reinterpret_cast<float4*>(Hs + lr * 36 + lc * 4) = hv;
        }
#pragma unroll
        for (int r = 0; r < 4; r++) {
            int j = lr + 32 * r;
            float4 wv = *reinterpret_cast<const float4*>(W + j * DIM + kt * 32 + lc * 4);
            Ws[(lc * 4 + 0) * 132 + j] = wv.x;
            Ws[(lc * 4 + 1) * 132 + j] = wv.y;
            Ws[(lc * 4 + 2) * 132 + j] = wv.z;
            Ws[(lc * 4 + 3) * 132 + j] = wv.w;
        }
        __syncthreads();

#pragma unroll
        for (int kk4 = 0; kk4 < 8; kk4++) {
            // 4 nodes x 4 kk of H (vector loads, warp-broadcast)
            float h[4][4];
#pragma unroll
            for (int i = 0; i < 4; i++) {
                *reinterpret_cast<float4*>(h[i]) =
                    *reinterpret_cast<const float4*>(Hs + (ng * 4 + i) * 36 + kk4 * 4);
            }
#pragma unroll
            for (int j = 0; j < 4; j++) {
                ulonglong2 wq = *reinterpret_cast<const ulonglong2*>(
                    Ws + (kk4 * 4 + j) * 132 + c0);
#pragma unroll
                for (int i = 0; i < 4; i++) {
                    unsigned long long hp = pack2(h[i][j], h[i][j]);
                    accp[i].x = fma2(hp, wq.x, accp[i].x);
                    accp[i].y = fma2(hp, wq.y, accp[i].y);
                }
            }
        }
        __syncthreads();
    }

#pragma unroll
    for (int i = 0; i < 4; i++) {
        float a0, a1, a2, a3;
        unpack2(accp[i].x, a0, a1);
        unpack2(accp[i].y, a2, a3);
        float v0 = fmaxf(a0 + bv[0], 0.f);
        float v1 = fmaxf(a1 + bv[1], 0.f);
        float v2 = fmaxf(a2 + bv[2], 0.f);
        float v3 = fmaxf(a3 + bv[3], 0.f);
        float ss = v0*v0 + v1*v1 + v2*v2 + v3*v3;
        ss += __shfl_xor_sync(FULLMASK, ss, 1);
        ss += __shfl_xor_sync(FULLMASK, ss, 2);
        float inv = rsqrtf(fmaxf(ss, 1e-24f));
        int gr = row0 + ng * 4 + i;
        if (gr < N_NODES) {
            *reinterpret_cast<float4*>(g_y + gr * DIM + c0) =
                make_float4(v0 * inv, v1 * inv, v2 * inv, v3 * inv);
        }
    }
}

// ---------------------------------------------------------------------------
extern "C" void kernel_launch(void* const* d_in, const int* in_sizes, int n_in,
                              void* d_out, int out_size)
{
    const float* x  = (const float*)d_in[0];
    const int*   nb = (const int*)  d_in[1];
    const float* w  = (const float*)d_in[2];
    const float* b  = (const float*)d_in[3];
    float* out = (float*)d_out;

    (void)in_sizes; (void)n_in; (void)out_size;

    int ncaps_total = N_NODES * NCAPS;
    normalize_kernel<<<(ncaps_total + 255) / 256, 256>>>(x);
    routing1_kernel<<<N_NODES / 4, 128>>>(nb);        // 50000 = 12500 * 4
    fc_kernel<<<(N_NODES + 31) / 32, 256>>>(w, b);
    routing2_kernel<<<N_NODES / 4, 128>>>(nb, out);
}

// round 11
// speedup vs baseline: 1.1761x; 1.0421x over previous
#include <cuda_runtime.h>

#define N_NODES 50000
#define M_NB    16
#define NCAPS   8
#define NHID    16
#define DIM     128
#define ROUTIT  6

#define FULLMASK 0xffffffffu

// Scratch (no allocation allowed): static device buffers.
__device__ float g_h1[N_NODES * DIM];  // layer-0 routing output (relu'd)
__device__ float g_y [N_NODES * DIM];  // normalize(relu(fc(h1)))

// ---- f32x2 packed helpers (sm_103a) ---------------------------------------
__device__ __forceinline__ unsigned long long fma2(unsigned long long a,
                                                   unsigned long long b,
                                                   unsigned long long c)
{
    unsigned long long d;
    asm("fma.rn.f32x2 %0, %1, %2, %3;" : "=l"(d) : "l"(a), "l"(b), "l"(c));
    return d;
}
__device__ __forceinline__ unsigned long long add2(unsigned long long a,
                                                   unsigned long long b)
{
    unsigned long long d;
    asm("add.rn.f32x2 %0, %1, %2;" : "=l"(d) : "l"(a), "l"(b));
    return d;
}
__device__ __forceinline__ unsigned long long mul2(unsigned long long a,
                                                   unsigned long long b)
{
    unsigned long long d;
    asm("mul.rn.f32x2 %0, %1, %2;" : "=l"(d) : "l"(a), "l"(b));
    return d;
}
__device__ __forceinline__ unsigned long long pack2(float lo, float hi)
{
    unsigned long long d;
    asm("mov.b64 %0, {%1, %2};" : "=l"(d) : "f"(lo), "f"(hi));
    return d;
}
__device__ __forceinline__ void unpack2(unsigned long long v, float& lo, float& hi)
{
    asm("mov.b64 {%0, %1}, %2;" : "=f"(lo), "=f"(hi) : "l"(v));
}

// ---------------------------------------------------------------------------
// Routing core, shared by both layers. Lane L: capsule k = L>>2, dg = L&3.
// z arrives already gathered+normalized in permuted slots:
//   slot s holds z of neighbor m = (s&~3)|((s&3)^dg)
// => butterfly reduce-scatter and p-allgather need NO runtime selects.
// After reduce-scatter, sdot[i] is the full dot for m = 4i + (dg^3).
// p = e / t computed PER-SLOT (each m keeps its own denominator), THEN
// allgathered depth-1: pB=xor2 ↔ dg^1, pC=xor1 ↔ dg^2, pD=xor3 ↔ dg.
// Slot c=0/1/2/3 uses pD/pB/pC/pA (compile-time mapping).
// ---------------------------------------------------------------------------
__device__ __forceinline__ void routing_core(ulonglong2* z, ulonglong2 xn,
                                             float* __restrict__ out, int node,
                                             int lane)
{
    const unsigned long long ZERO = 0;
    ulonglong2 u = xn;
    ulonglong2 unew = xn;

#pragma unroll
    for (int it = 0; it < ROUTIT; it++) {
        // ---- phase A: partial dots (own 4 dims) for each slot ----
        float a[M_NB];
#pragma unroll
        for (int s = 0; s < M_NB; s++) {
            unsigned long long acc = fma2(z[s].x, u.x, fma2(z[s].y, u.y, ZERO));
            float lo, hi; unpack2(acc, lo, hi);
            a[s] = lo + hi;
        }

        // ---- select-free reduce-scatter over the 4 dg-lanes ----
        float b[8];
#pragma unroll
        for (int i = 0; i < 4; i++) {
#pragma unroll
            for (int c0 = 0; c0 < 2; c0++) {
                b[2*i + c0] = a[4*i + (c0 ^ 2)]
                            + __shfl_xor_sync(FULLMASK, a[4*i + c0], 2);
            }
        }
        float sdot[4];
#pragma unroll
        for (int i = 0; i < 4; i++) {
            sdot[i] = b[2*i + 1] + __shfl_xor_sync(FULLMASK, b[2*i + 0], 1);
        }
        // sdot[i] = <z[m], u> for m = 4*i + (dg^3).

        // ---- softmax over k (8 lanes, stride 4). |s|<=1 (unit vectors):
        //      shift-invariant softmax needs no max subtraction. ----
        float e[4], t[4];
#pragma unroll
        for (int i = 0; i < 4; i++) { e[i] = __expf(sdot[i]); t[i] = e[i]; }
#pragma unroll
        for (int i = 0; i < 4; i++) t[i] += __shfl_xor_sync(FULLMASK, t[i], 4);
#pragma unroll
        for (int i = 0; i < 4; i++) t[i] += __shfl_xor_sync(FULLMASK, t[i], 8);
#pragma unroll
        for (int i = 0; i < 4; i++) t[i] += __shfl_xor_sync(FULLMASK, t[i], 16);
        float pA[4];
#pragma unroll
        for (int i = 0; i < 4; i++) pA[i] = __fdividef(e[i], t[i]);
        // pA[i] ↔ m-offset dg^3 (per-m denominator applied per slot).

        // ---- depth-1 allgather of p over the dg-group ----
        float pB[4], pC[4], pD[4];
#pragma unroll
        for (int i = 0; i < 4; i++) pB[i] = __shfl_xor_sync(FULLMASK, pA[i], 2); // offset dg^1
#pragma unroll
        for (int i = 0; i < 4; i++) pC[i] = __shfl_xor_sync(FULLMASK, pA[i], 1); // offset dg^2
#pragma unroll
        for (int i = 0; i < 4; i++) pD[i] = __shfl_xor_sync(FULLMASK, pA[i], 3); // offset dg

        // ---- phase B: unew = xn + sum_m p[m] * z[m] (packed, 2 chains) ----
        ulonglong2 accA = xn;
        ulonglong2 accB; accB.x = ZERO; accB.y = ZERO;
#pragma unroll
        for (int i = 0; i < 4; i++) {
            unsigned long long w0 = pack2(pD[i], pD[i]);   // slot c=0 ↔ offset dg
            accA.x = fma2(z[4*i + 0].x, w0, accA.x);
            accA.y = fma2(z[4*i + 0].y, w0, accA.y);
            unsigned long long w1 = pack2(pB[i], pB[i]);   // slot c=1 ↔ dg^1
            accA.x = fma2(z[4*i + 1].x, w1, accA.x);
            accA.y = fma2(z[4*i + 1].y, w1, accA.y);
            unsigned long long w2 = pack2(pC[i], pC[i]);   // slot c=2 ↔ dg^2
            accB.x = fma2(z[4*i + 2].x, w2, accB.x);
            accB.y = fma2(z[4*i + 2].y, w2, accB.y);
            unsigned long long w3 = pack2(pA[i], pA[i]);   // slot c=3 ↔ dg^3
            accB.x = fma2(z[4*i + 3].x, w3, accB.x);
            accB.y = fma2(z[4*i + 3].y, w3, accB.y);
        }
        unew.x = add2(accA.x, accB.x);
        unew.y = add2(accA.y, accB.y);

        if (it < ROUTIT - 1) {
            // per-capsule renormalize: ||unew||^2 over the 4 dg-lanes
            unsigned long long sq = fma2(unew.x, unew.x, fma2(unew.y, unew.y, ZERO));
            float lo, hi; unpack2(sq, lo, hi);
            float nsq = lo + hi;
            nsq += __shfl_xor_sync(FULLMASK, nsq, 1);
            nsq += __shfl_xor_sync(FULLMASK, nsq, 2);
            float inv = rsqrtf(fmaxf(nsq, 1e-24f));
            unsigned long long invp = pack2(inv, inv);
            u.x = mul2(unew.x, invp);
            u.y = mul2(unew.y, invp);
        }
    }

    // relu + store
    float f0, f1, f2, f3;
    unpack2(unew.x, f0, f1);
    unpack2(unew.y, f2, f3);
    float4 o;
    o.x = fmaxf(f0, 0.f); o.y = fmaxf(f1, 0.f);
    o.z = fmaxf(f2, 0.f); o.w = fmaxf(f3, 0.f);
    reinterpret_cast<float4*>(out)[node * 32 + lane] = o;
}

// ---------------------------------------------------------------------------
// Layer 1: reads RAW x, normalizes self row + gathered rows in registers
// (fused normalize — no separate kernel, no g_xn buffer).
// Norm reduce over the dg-group with permuted slots is select-free:
//   lane dg, slot s holds m = s^dg; partner dg^1 holds same m in slot s^1
//   => q1[s] = q[s] + shfl_xor(q[s^1],1); q2[s] = q1[s] + shfl_xor(q1[s^2],2)
// sums all 4 partial capsule norms of (m, k) with compile-time indices.
// ---------------------------------------------------------------------------
__global__ __launch_bounds__(128, 5) void routing1_kernel(const float* __restrict__ x,
                                                          const int*   __restrict__ nb)
{
    const int lane = threadIdx.x & 31;
    const int node = blockIdx.x * 4 + (threadIdx.x >> 5);
    const int dg   = lane & 3;
    const unsigned long long ZERO = 0;

    int nbv = 0;
    if (lane < 16) nbv = nb[node * M_NB + lane];

    const ulonglong2* srcv = reinterpret_cast<const ulonglong2*>(x);

    // self row: normalize per capsule (reduce over dg-group)
    ulonglong2 xr = srcv[node * 32 + lane];
    {
        unsigned long long sq = fma2(xr.x, xr.x, fma2(xr.y, xr.y, ZERO));
        float lo, hi; unpack2(sq, lo, hi);
        float nsq = lo + hi;
        nsq += __shfl_xor_sync(FULLMASK, nsq, 1);
        nsq += __shfl_xor_sync(FULLMASK, nsq, 2);
        float inv = rsqrtf(fmaxf(nsq, 1e-24f));
        unsigned long long invp = pack2(inv, inv);
        xr.x = mul2(xr.x, invp);
        xr.y = mul2(xr.y, invp);
    }

    // gather raw neighbor rows into permuted slots
    ulonglong2 z[M_NB];
#pragma unroll
    for (int s = 0; s < M_NB; s++) {
        int row = __shfl_sync(FULLMASK, nbv, s ^ dg);
        z[s] = srcv[row * 32 + lane];
    }

    // per-slot partial capsule norms, then select-free 2-level reduce
    float q[M_NB];
#pragma unroll
    for (int s = 0; s < M_NB; s++) {
        unsigned long long sq = fma2(z[s].x, z[s].x, fma2(z[s].y, z[s].y, ZERO));
        float lo, hi; unpack2(sq, lo, hi);
        q[s] = lo + hi;
    }
    float q1[M_NB];
#pragma unroll
    for (int s = 0; s < M_NB; s++)
        q1[s] = q[s] + __shfl_xor_sync(FULLMASK, q[s ^ 1], 1);
#pragma unroll
    for (int s = 0; s < M_NB; s++) {
        float q2 = q1[s] + __shfl_xor_sync(FULLMASK, q1[s ^ 2], 2);
        float inv = rsqrtf(fmaxf(q2, 1e-24f));
        unsigned long long invp = pack2(inv, inv);
        z[s].x = mul2(z[s].x, invp);
        z[s].y = mul2(z[s].y, invp);
    }

    routing_core(z, xr, g_h1, node, lane);
}

// ---------------------------------------------------------------------------
// Layer 2: input g_y already per-capsule normalized (fc epilogue).
// ---------------------------------------------------------------------------
__global__ __launch_bounds__(128, 5) void routing2_kernel(const int* __restrict__ nb,
                                                          float* __restrict__ out)
{
    const int lane = threadIdx.x & 31;
    const int node = blockIdx.x * 4 + (threadIdx.x >> 5);
    const int dg   = lane & 3;

    int nbv = 0;
    if (lane < 16) nbv = nb[node * M_NB + lane];

    const ulonglong2* srcv = reinterpret_cast<const ulonglong2*>(g_y);

    ulonglong2 xn = srcv[node * 32 + lane];

    ulonglong2 z[M_NB];
#pragma unroll
    for (int s = 0; s < M_NB; s++) {
        int row = __shfl_sync(FULLMASK, nbv, s ^ dg);
        z[s] = srcv[row * 32 + lane];
    }

    routing_core(z, xn, out, node, lane);
}

// ---------------------------------------------------------------------------
// K3: y = normalize_per_capsule( relu( h1 @ W^T + b ) )  -> g_y
// Block: 128 nodes x 128 cols, 256 threads. Each warp handles 16 nodes;
// each thread 16 nodes x 4 cols (acc in packed f32x2). W tile (32 k) loaded
// once per kt and amortized over 128 nodes; h loads are warp-broadcast
// LDS.128 (conflict-degree 1). Per kk4 group: 20 LDS vs 128 fma2.
// ---------------------------------------------------------------------------
#define FC_NODES 128

__global__ __launch_bounds__(256, 2) void fc_kernel(const float* __restrict__ W,
                                                    const float* __restrict__ bias)
{
    __shared__ __align__(16) float Hs[FC_NODES * 36];   // Hs[node*36 + kk]
    __shared__ __align__(16) float Ws[32 * 132];        // Ws[kk*132 + j] (transposed)

    const int t    = threadIdx.x;
    const int row0 = blockIdx.x * FC_NODES;
    const int ng   = t >> 5;        // warp id: nodes ng*16 .. ng*16+15
    const int cg   = t & 31;        // col group (4 cols)
    const int c0   = cg * 4;

    ulonglong2 acc[16];
#pragma unroll
    for (int i = 0; i < 16; i++) { acc[i].x = 0ull; acc[i].y = 0ull; }

    float bv[4];
#pragma unroll
    for (int j = 0; j < 4; j++) bv[j] = bias[c0 + j];

    const int lr = t >> 3;          // 0..31
    const int lc = t & 7;           // 0..7

    for (int kt = 0; kt < 4; kt++) {
        // H tile: 128 nodes x 32 k (each thread 4 float4s)
#pragma unroll
        for (int r = 0; r < 4; r++) {
            int idx  = r * 256 + t;         // 0..1023
            int nd   = idx >> 3;            // 0..127
            int lcc  = idx & 7;             // 0..7
            int gr   = row0 + nd;
            float4 hv = make_float4(0.f, 0.f, 0.f, 0.f);
            if (gr < N_NODES)
                hv = *reinterpret_cast<const float4*>(g_h1 + gr * DIM + kt * 32 + lcc * 4);
            *reinterpret_cast<float4*>(Hs + nd * 36 + lcc * 4) = hv;
        }
        // W tile transposed: Ws[kk][j]
#pragma unroll
        for (int r = 0; r < 4; r++) {
            int j = lr + 32 * r;
            float4 wv = *reinterpret_cast<const float4*>(W + j * DIM + kt * 32 + lc * 4);
            Ws[(lc * 4 + 0) * 132 + j] = wv.x;
            Ws[(lc * 4 + 1) * 132 + j] = wv.y;
            Ws[(lc * 4 + 2) * 132 + j] = wv.z;
            Ws[(lc * 4 + 3) * 132 + j] = wv.w;
        }
        __syncthreads();

#pragma unroll
        for (int kk4 = 0; kk4 < 8; kk4++) {
            ulonglong2 wq[4];
#pragma unroll
            for (int j2 = 0; j2 < 4; j2++)
                wq[j2] = *reinterpret_cast<const ulonglong2*>(
                    Ws + (kk4 * 4 + j2) * 132 + c0);
#pragma unroll
            for (int i = 0; i < 16; i++) {
                float4 h = *reinterpret_cast<const float4*>(
                    Hs + (ng * 16 + i) * 36 + kk4 * 4);
                unsigned long long h0 = pack2(h.x, h.x);
                acc[i].x = fma2(h0, wq[0].x, acc[i].x);
                acc[i].y = fma2(h0, wq[0].y, acc[i].y);
                unsigned long long h1 = pack2(h.y, h.y);
                acc[i].x = fma2(h1, wq[1].x, acc[i].x);
                acc[i].y = fma2(h1, wq[1].y, acc[i].y);
                unsigned long long h2 = pack2(h.z, h.z);
                acc[i].x = fma2(h2, wq[2].x, acc[i].x);
                acc[i].y = fma2(h2, wq[2].y, acc[i].y);
                unsigned long long h3 = pack2(h.w, h.w);
                acc[i].x = fma2(h3, wq[3].x, acc[i].x);
                acc[i].y = fma2(h3, wq[3].y, acc[i].y);
            }
        }
        __syncthreads();
    }

    // Epilogue: bias + relu + per-capsule normalize (4 cg-lanes per capsule)
#pragma unroll
    for (int i = 0; i < 16; i++) {
        float a0, a1, a2, a3;
        unpack2(acc[i].x, a0, a1);
        unpack2(acc[i].y, a2, a3);
        float v0 = fmaxf(a0 + bv[0], 0.f);
        float v1 = fmaxf(a1 + bv[1], 0.f);
        float v2 = fmaxf(a2 + bv[2], 0.f);
        float v3 = fmaxf(a3 + bv[3], 0.f);
        float ss = v0*v0 + v1*v1 + v2*v2 + v3*v3;
        ss += __shfl_xor_sync(FULLMASK, ss, 1);
        ss += __shfl_xor_sync(FULLMASK, ss, 2);
        float inv = rsqrtf(fmaxf(ss, 1e-24f));
        int gr = row0 + ng * 16 + i;
        if (gr < N_NODES) {
            *reinterpret_cast<float4*>(g_y + gr * DIM + c0) =
                make_float4(v0 * inv, v1 * inv, v2 * inv, v3 * inv);
        }
    }
}

// ---------------------------------------------------------------------------
extern "C" void kernel_launch(void* const* d_in, const int* in_sizes, int n_in,
                              void* d_out, int out_size)
{
    const float* x  = (const float*)d_in[0];
    const int*   nb = (const int*)  d_in[1];
    const float* w  = (const float*)d_in[2];
    const float* b  = (const float*)d_in[3];
    float* out = (float*)d_out;

    (void)in_sizes; (void)n_in; (void)out_size;

    routing1_kernel<<<N_NODES / 4, 128>>>(x, nb);     // 50000 = 12500 * 4
    fc_kernel<<<(N_NODES + FC_NODES - 1) / FC_NODES, 256>>>(w, b);
    routing2_kernel<<<N_NODES / 4, 128>>>(nb, out);
}